// round 9
// baseline (speedup 1.0000x reference)
#include <cuda_runtime.h>

// ============================================================================
// Triaffine: s[b,z,x,y] = sum_{i,k,j} xb[b,x,i] * z[b,z,k] * W[i,k,j] * yb[b,y,j]
//   B=8, S=128, D=512, I=J=513 (bias), K=512, W layout [i][k][j] row-major.
// 3 stages, fp32 with packed fma.rn.f32x2, software-pipelined (cp.async double
// buffering for B, register prefetch for A, A stored duplicated so each
// LDS.128 yields two packed f32x2 operands — no per-kk MOVs).
//   k1: Xw[bx, k*513+j] = xb_all[1024,513] @ W[513, 262656]
//   k2: T[bx, z, j]     = z[b][128,512]    @ Xw[bx][512,513]
//   k3: out[b,z,x,y]    = T[bx][128,513]   @ yb[b][128,513]^T
// ============================================================================

#define BM 128
#define BN 128
#define BK 16

#define NIN   512
#define IDIM  513                 // NIN + bias
#define NW    262656              // 512*513  (k,j) flattened
#define TROW  65664               // 128*513

// Scratch (device globals — allocation-free per harness rules)
__device__ float g_Xw[268959744]; // 1024 * 262656 floats (~1.08 GB)
__device__ float g_T [67239936];  // 1024 * 128 * 513 floats (~269 MB)

static __device__ __forceinline__ unsigned sptr(const void* p) {
    return (unsigned)__cvta_generic_to_shared(p);
}

#define CP_ASYNC16Z(s, g, sz) \
    asm volatile("cp.async.ca.shared.global [%0], [%1], 16, %2;\n" :: "r"(s), "l"(g), "r"(sz))
#define CP_ASYNC4Z(s, g, sz) \
    asm volatile("cp.async.ca.shared.global [%0], [%1], 4, %2;\n"  :: "r"(s), "l"(g), "r"(sz))
#define CP_COMMIT asm volatile("cp.async.commit_group;\n" ::: "memory")
#define CP_WAIT0  asm volatile("cp.async.wait_group 0;\n"  ::: "memory")

// 8x8 per-thread micro-kernel over a BK slice. A is stored duplicated:
// As2[kk][2m]=As2[kk][2m+1]=a[m], so a 16B LDS gives two packed b64 operands.
static __device__ __forceinline__ void mma_step2(
    const float (&As2)[BK][2 * BM], const float (&Bs)[BK][BN],
    unsigned long long (&acc)[8][4], int tx, int ty)
{
#pragma unroll
    for (int kk = 0; kk < BK; kk++) {
        ulonglong2 a01 = *reinterpret_cast<const ulonglong2*>(&As2[kk][ty * 16 + 0]);
        ulonglong2 a23 = *reinterpret_cast<const ulonglong2*>(&As2[kk][ty * 16 + 4]);
        ulonglong2 a45 = *reinterpret_cast<const ulonglong2*>(&As2[kk][ty * 16 + 8]);
        ulonglong2 a67 = *reinterpret_cast<const ulonglong2*>(&As2[kk][ty * 16 + 12]);
        ulonglong2 b01 = *reinterpret_cast<const ulonglong2*>(&Bs[kk][tx * 8]);
        ulonglong2 b23 = *reinterpret_cast<const ulonglong2*>(&Bs[kk][tx * 8 + 4]);
        unsigned long long ap[8] = {a01.x, a01.y, a23.x, a23.y, a45.x, a45.y, a67.x, a67.y};
        unsigned long long bp[4] = {b01.x, b01.y, b23.x, b23.y};
#pragma unroll
        for (int i = 0; i < 8; i++) {
            asm("fma.rn.f32x2 %0, %1, %2, %0;" : "+l"(acc[i][0]) : "l"(ap[i]), "l"(bp[0]));
            asm("fma.rn.f32x2 %0, %1, %2, %0;" : "+l"(acc[i][1]) : "l"(ap[i]), "l"(bp[1]));
            asm("fma.rn.f32x2 %0, %1, %2, %0;" : "+l"(acc[i][2]) : "l"(ap[i]), "l"(bp[2]));
            asm("fma.rn.f32x2 %0, %1, %2, %0;" : "+l"(acc[i][3]) : "l"(ap[i]), "l"(bp[3]));
        }
    }
}

// ----------------------------------------------------------------------------
// k1: Xw = xb_all @ W.  grid = (8 m-tiles, 2052 n-tiles), m fastest so the 8
// CTAs sharing one W column-panel are wave-adjacent (W read ~once from DRAM).
// ----------------------------------------------------------------------------
__global__ __launch_bounds__(256, 2)
void triaffine_k1(const float* __restrict__ x, const float* __restrict__ W)
{
    __shared__ float As2[2][BK][2 * BM];  // 32 KB
    __shared__ float Bs [2][BK][BN];      // 16 KB
    const int       m0 = blockIdx.x * BM;
    const long long n0 = (long long)blockIdx.y * BN;
    const int tid = threadIdx.x;
    const int tx = tid & 15, ty = tid >> 4;
    const int a_row = tid >> 1;
    const int a_k   = (tid & 1) * 8;

    unsigned long long acc[8][4];
#pragma unroll
    for (int i = 0; i < 8; i++)
#pragma unroll
        for (int j = 0; j < 4; j++) acc[i][j] = 0ull;

    const long long arow = (long long)(m0 + a_row) * NIN;

    // A tile (k0..k0+15) for this thread -> 8 regs
    auto ldA = [&](int k0, float (&v)[8]) {
        int kb = k0 + a_k;
        if (kb + 7 < NIN) {
            float4 v0 = *reinterpret_cast<const float4*>(x + arow + kb);
            float4 v1 = *reinterpret_cast<const float4*>(x + arow + kb + 4);
            v[0] = v0.x; v[1] = v0.y; v[2] = v0.z; v[3] = v0.w;
            v[4] = v1.x; v[5] = v1.y; v[6] = v1.z; v[7] = v1.w;
        } else {
#pragma unroll
            for (int u = 0; u < 8; u++) {
                int i = kb + u;
                v[u] = (i < NIN) ? x[arow + i] : (i == NIN ? 1.0f : 0.0f);
            }
        }
    };
    auto stA = [&](int buf, const float (&v)[8]) {
#pragma unroll
        for (int u = 0; u < 8; u++)
            *reinterpret_cast<float2*>(&As2[buf][a_k + u][2 * a_row]) = make_float2(v[u], v[u]);
    };
    // B tile via cp.async (zfill for rows i >= IDIM)
    auto cpB = [&](int k0, int buf) {
#pragma unroll
        for (int c = tid; c < 512; c += 256) {
            int r = c >> 5, col = (c & 31) * 4;
            int i = k0 + r;
            int ic = i < IDIM ? i : IDIM - 1;
            const float* g = W + (long long)ic * NW + n0 + col;
            int sz = (i < IDIM) ? 16 : 0;
            CP_ASYNC16Z(sptr(&Bs[buf][r][col]), g, sz);
        }
    };

    float av[8];
    ldA(0, av);
    cpB(0, 0);
    CP_COMMIT;
    stA(0, av);

    int buf = 0;
    for (int t = 0; t < 33; t++) {
        CP_WAIT0;
        __syncthreads();
        if (t < 32) {
            ldA((t + 1) * BK, av);
            cpB((t + 1) * BK, buf ^ 1);
            CP_COMMIT;
        }
        mma_step2(As2[buf], Bs[buf], acc, tx, ty);
        if (t < 32) stA(buf ^ 1, av);
        buf ^= 1;
    }

#pragma unroll
    for (int i = 0; i < 8; i++) {
        float* crow = g_Xw + (long long)(m0 + ty * 8 + i) * NW + n0 + tx * 8;
        ulonglong2 r0; r0.x = acc[i][0]; r0.y = acc[i][1];
        ulonglong2 r1; r1.x = acc[i][2]; r1.y = acc[i][3];
        *reinterpret_cast<ulonglong2*>(crow)     = r0;
        *reinterpret_cast<ulonglong2*>(crow + 4) = r1;
    }
}

// ----------------------------------------------------------------------------
// k2: T[bx] = z[b] @ Xw[bx].  grid = (5 n-tiles, 1024 bx). N=513 -> guarded.
// Xw rows are only 4B-aligned (pitch 513 floats) -> cp.async 4B with zfill.
// ----------------------------------------------------------------------------
__global__ __launch_bounds__(256, 2)
void triaffine_k2(const float* __restrict__ zin)
{
    __shared__ float As2[2][BK][2 * BM];
    __shared__ float Bs [2][BK][BN];
    const int bx = blockIdx.y;
    const int b  = bx >> 7;
    const int n0 = blockIdx.x * BN;
    const int tid = threadIdx.x;
    const int tx = tid & 15, ty = tid >> 4;
    const int a_row = tid >> 1;
    const int a_k   = (tid & 1) * 8;

    unsigned long long acc[8][4];
#pragma unroll
    for (int i = 0; i < 8; i++)
#pragma unroll
        for (int j = 0; j < 4; j++) acc[i][j] = 0ull;

    const long long zrow  = ((long long)b * 128 + a_row) * NIN;
    const float*    Bbase = g_Xw + (long long)bx * NW;

    auto ldA = [&](int k0, float (&v)[8]) {
        float4 v0 = *reinterpret_cast<const float4*>(zin + zrow + k0 + a_k);
        float4 v1 = *reinterpret_cast<const float4*>(zin + zrow + k0 + a_k + 4);
        v[0] = v0.x; v[1] = v0.y; v[2] = v0.z; v[3] = v0.w;
        v[4] = v1.x; v[5] = v1.y; v[6] = v1.z; v[7] = v1.w;
    };
    auto stA = [&](int buf, const float (&v)[8]) {
#pragma unroll
        for (int u = 0; u < 8; u++)
            *reinterpret_cast<float2*>(&As2[buf][a_k + u][2 * a_row]) = make_float2(v[u], v[u]);
    };
    auto cpB = [&](int k0, int buf) {
#pragma unroll
        for (int q = 0; q < 8; q++) {
            int c = tid + 256 * q;
            int r = c >> 7, col = c & 127;
            int n = n0 + col;
            int nc = n < IDIM ? n : IDIM - 1;
            const float* g = Bbase + (long long)(k0 + r) * IDIM + nc;
            int sz = (n < IDIM) ? 4 : 0;
            CP_ASYNC4Z(sptr(&Bs[buf][r][col]), g, sz);
        }
    };

    float av[8];
    ldA(0, av);
    cpB(0, 0);
    CP_COMMIT;
    stA(0, av);

    int buf = 0;
    for (int t = 0; t < 32; t++) {           // K = 512 exactly
        CP_WAIT0;
        __syncthreads();
        if (t < 31) {
            ldA((t + 1) * BK, av);
            cpB((t + 1) * BK, buf ^ 1);
            CP_COMMIT;
        }
        mma_step2(As2[buf], Bs[buf], acc, tx, ty);
        if (t < 31) stA(buf ^ 1, av);
        buf ^= 1;
    }

    float* Tb = g_T + (long long)bx * TROW;
#pragma unroll
    for (int i = 0; i < 8; i++) {
        int zz = ty * 8 + i;
#pragma unroll
        for (int j = 0; j < 4; j++) {
            int c0 = n0 + tx * 8 + 2 * j;
            float lo = __uint_as_float((unsigned)(acc[i][j] & 0xffffffffull));
            float hi = __uint_as_float((unsigned)(acc[i][j] >> 32));
            if (c0 < IDIM)     Tb[zz * IDIM + c0]     = lo;
            if (c0 + 1 < IDIM) Tb[zz * IDIM + c0 + 1] = hi;
        }
    }
}

// ----------------------------------------------------------------------------
// k3: out[b,z,xx,y] = T[bx] @ yb[b]^T.  grid = 1024 bx, one 128x128 tile each.
// Both operands need transpose into SMEM -> register prefetch for both.
// ----------------------------------------------------------------------------
__global__ __launch_bounds__(256, 2)
void triaffine_k3(const float* __restrict__ yin, float* __restrict__ out)
{
    __shared__ float As2[2][BK][2 * BM];
    __shared__ float Bs [2][BK][BN];
    const int bx = blockIdx.x;
    const int b  = bx >> 7;
    const int xx = bx & 127;
    const int tid = threadIdx.x;
    const int tx = tid & 15, ty = tid >> 4;
    const int a_row = tid >> 1;
    const int a_k   = (tid & 1) * 8;

    unsigned long long acc[8][4];
#pragma unroll
    for (int i = 0; i < 8; i++)
#pragma unroll
        for (int j = 0; j < 4; j++) acc[i][j] = 0ull;

    const float*    Ta   = g_T + (long long)bx * TROW + (long long)a_row * IDIM;
    const long long yrow = ((long long)b * 128 + a_row) * NIN;

    auto ldAB = [&](int k0, float (&va)[8], float (&vb)[8]) {
        int jb = k0 + a_k;
        if (jb + 7 < NIN) {
#pragma unroll
            for (int u = 0; u < 8; u++) va[u] = Ta[jb + u];
            float4 v0 = *reinterpret_cast<const float4*>(yin + yrow + jb);
            float4 v1 = *reinterpret_cast<const float4*>(yin + yrow + jb + 4);
            vb[0] = v0.x; vb[1] = v0.y; vb[2] = v0.z; vb[3] = v0.w;
            vb[4] = v1.x; vb[5] = v1.y; vb[6] = v1.z; vb[7] = v1.w;
        } else {
#pragma unroll
            for (int u = 0; u < 8; u++) {
                int j = jb + u;
                va[u] = (j < IDIM) ? Ta[j] : 0.0f;
                vb[u] = (j < NIN) ? yin[yrow + j] : (j == NIN ? 1.0f : 0.0f);
            }
        }
    };
    auto stAB = [&](int buf, const float (&va)[8], const float (&vb)[8]) {
#pragma unroll
        for (int u = 0; u < 8; u++) {
            *reinterpret_cast<float2*>(&As2[buf][a_k + u][2 * a_row]) = make_float2(va[u], va[u]);
            Bs[buf][a_k + u][a_row] = vb[u];
        }
    };

    float av[8], bv[8];
    ldAB(0, av, bv);
    stAB(0, av, bv);

    int buf = 0;
    for (int t = 0; t < 33; t++) {
        __syncthreads();
        if (t < 32) ldAB((t + 1) * BK, av, bv);
        mma_step2(As2[buf], Bs[buf], acc, tx, ty);
        if (t < 32) stAB(buf ^ 1, av, bv);
        buf ^= 1;
    }

#pragma unroll
    for (int i = 0; i < 8; i++) {
        int zz = ty * 8 + i;
        float* o = out + ((((long long)b * 128 + zz) * 128) + xx) * 128 + tx * 8;
        ulonglong2 r0; r0.x = acc[i][0]; r0.y = acc[i][1];
        ulonglong2 r1; r1.x = acc[i][2]; r1.y = acc[i][3];
        *reinterpret_cast<ulonglong2*>(o)     = r0;
        *reinterpret_cast<ulonglong2*>(o + 4) = r1;
    }
}

// ----------------------------------------------------------------------------

extern "C" void kernel_launch(void* const* d_in, const int* in_sizes, int n_in,
                              void* d_out, int out_size)
{
    const float* x = (const float*)d_in[0];
    const float* y = (const float*)d_in[1];
    const float* z = (const float*)d_in[2];
    const float* w = (const float*)d_in[3];
    float* out = (float*)d_out;

    // Stage 1: Xw = xb_all @ W   (276 GFLOP)
    triaffine_k1<<<dim3(8, 2052), 256>>>(x, w);
    // Stage 2: T[bx] = z[b] @ Xw[bx]   (69 GFLOP)
    triaffine_k2<<<dim3(5, 1024), 256>>>(z);
    // Stage 3: out = T @ yb^T   (17 GFLOP)
    triaffine_k3<<<dim3(1024), 256>>>(y, out);
}

// round 15
// speedup vs baseline: 2.9729x; 2.9729x over previous
#include <cuda_runtime.h>
#include <cuda_bf16.h>
#include <cstdint>

// ============================================================================
// Triaffine via mma.sync (HMMA, plain sm_103-compatible PTX), bf16 hi/lo split.
//   s[b,z,x,y] = sum_{i,k,j} xb[b,x,i] z[b,z,k] W[i,k,j] yb[b,y,j]
// Pipeline:
//   cv_split: x,y -> bf16 hi/lo [1024][576] (bias@512, pad 0); z -> [1024][512]
//   cv_wt   : W[i][k][j] -> WT[(j*512+k)][i] hi/lo, i padded to 576
//   g1: Xw[m][j*512+k] = xb[m][i]   . WT[(j,k)][i]   M=1024 N=262656 K=576
//   g2: T [bx][z][j]   = z[b][z][k] . Xw[bx][j*512+k]  per bx: 128x513x512
//   g3: out[b,z,x,y]   = T[bx][z][j]. yb[b][y][j]      per bx: 128x128x576
// Every fp32 product = 3 bf16 mma.sync products (Ah.Bh + Ah.Bl + Al.Bh) into
// shared fp32 accumulators. CTA tile 128x128, k-chunks of 32, cp.async double
// buffering, 8 warps x (64x32) warp tiles, m16n8k16 + ldmatrix.
// ============================================================================

#define NIN  512
#define IDIM 513
#define KPAD 576
#define NWL  262656LL   // 513*512  (j,k) flat
#define TP   576

// -------------------- scratch (device globals, zero-initialized) ------------
__device__ __nv_bfloat16 g_xh[1024 * KPAD], g_xl[1024 * KPAD];
__device__ __nv_bfloat16 g_yh[1024 * KPAD], g_yl[1024 * KPAD];
__device__ __nv_bfloat16 g_zh[1024 * NIN],  g_zl[1024 * NIN];
__device__ __nv_bfloat16 g_Wh[(size_t)NWL * KPAD], g_Wl[(size_t)NWL * KPAD];
__device__ __nv_bfloat16 g_Xh[(size_t)1024 * NWL], g_Xl[(size_t)1024 * NWL];
__device__ __nv_bfloat16 g_Th[(size_t)1024 * 128 * TP], g_Tl[(size_t)1024 * 128 * TP];

// -------------------- PTX helpers ------------------------------------------
static __device__ __forceinline__ uint32_t smem_u32(const void* p) {
    uint32_t a;
    asm("{ .reg .u64 t; cvta.to.shared.u64 t, %1; cvt.u32.u64 %0, t; }"
        : "=r"(a) : "l"(p));
    return a;
}
#define CPA16(s, g) \
    asm volatile("cp.async.ca.shared.global [%0], [%1], 16;" :: "r"(s), "l"(g))
#define CP_COMMIT() asm volatile("cp.async.commit_group;" ::: "memory")
#define CP_WAITG1() asm volatile("cp.async.wait_group 1;" ::: "memory")

#define LDSM4(r, a) \
    asm volatile("ldmatrix.sync.aligned.m8n8.x4.shared.b16 {%0,%1,%2,%3}, [%4];" \
        : "=r"((r)[0]), "=r"((r)[1]), "=r"((r)[2]), "=r"((r)[3]) : "r"(a))

#define MMA16816(c, A, b0, b1) \
    asm volatile("mma.sync.aligned.m16n8k16.row.col.f32.bf16.bf16.f32 " \
        "{%0,%1,%2,%3}, {%4,%5,%6,%7}, {%8,%9}, {%0,%1,%2,%3};" \
        : "+f"((c)[0]), "+f"((c)[1]), "+f"((c)[2]), "+f"((c)[3]) \
        : "r"((A)[0]), "r"((A)[1]), "r"((A)[2]), "r"((A)[3]), "r"(b0), "r"(b1))

// fp32 pair -> packed bf16x2 hi word + lo (residual) word
static __device__ __forceinline__ void hl_pack(float v0, float v1,
                                               uint32_t& hw, uint32_t& lw) {
    __nv_bfloat16 h0 = __float2bfloat16(v0), h1 = __float2bfloat16(v1);
    __nv_bfloat16 l0 = __float2bfloat16(v0 - __bfloat162float(h0));
    __nv_bfloat16 l1 = __float2bfloat16(v1 - __bfloat162float(h1));
    hw = (uint32_t)__bfloat16_as_ushort(h0) | ((uint32_t)__bfloat16_as_ushort(h1) << 16);
    lw = (uint32_t)__bfloat16_as_ushort(l0) | ((uint32_t)__bfloat16_as_ushort(l1) << 16);
}

// -------------------- SMEM geometry -----------------------------------------
// Per buffer: Ah[128][40], Al, Bh[128][40], Bl bf16 (pitch 40 elems = 80 B,
// conflict-free for ldmatrix). Tile offsets 0 / 10240 / 20480 / 30720 B.
#define PITCHB 80
#define T_AL   10240u
#define T_BH   20480u
#define T_BL   30720u
#define BUFB   40960u
#define SMEMB  (2 * 40960)

// -------------------- generic double-buffered mma.sync GEMM body ------------
// fill(ch, dst_base): issue 8 x cp.async(16B) for chunk ch into buffer.
// epi(acc): write back. acc[mi][ni][4] covers warp tile 64x32.
template <int NC, class F, class E>
static __device__ __forceinline__ void mm_body(F&& fill, E&& epi) {
    extern __shared__ char dsm[];
    const uint32_t sb = smem_u32(dsm);
    const int lane = threadIdx.x & 31, wid = threadIdx.x >> 5;
    const int wm = wid & 1, wn = wid >> 1;     // warp tile: (wm*64, wn*32)

    float acc[4][4][4];
#pragma unroll
    for (int i = 0; i < 4; i++)
#pragma unroll
        for (int j = 0; j < 4; j++)
#pragma unroll
            for (int q = 0; q < 4; q++) acc[i][j][q] = 0.0f;

    fill(0, sb);          CP_COMMIT();
    fill(1, sb + BUFB);   CP_COMMIT();

    // ldmatrix lane offsets
    const uint32_t a_off = (uint32_t)((lane & 15) * PITCHB + (lane >> 4) * 16);
    const uint32_t b_off = (uint32_t)((((lane >> 4) * 8) + (lane & 7)) * PITCHB
                                      + ((lane >> 3) & 1) * 16);

    for (int c = 0; c < NC; c++) {
        CP_WAITG1();
        __syncthreads();
        const uint32_t bb = sb + (uint32_t)(c & 1) * BUFB;

#pragma unroll
        for (int ks = 0; ks < 2; ks++) {
            const uint32_t kb = (uint32_t)(ks * 32);
            uint32_t Ah[4][4], Al[4][4];
#pragma unroll
            for (int mi = 0; mi < 4; mi++) {
                uint32_t ra = bb + (uint32_t)((wm * 64 + mi * 16) * PITCHB) + a_off + kb;
                LDSM4(Ah[mi], ra);
                LDSM4(Al[mi], ra + T_AL);
            }
            uint32_t Bh[4][2], Bl[4][2];
#pragma unroll
            for (int p = 0; p < 2; p++) {
                uint32_t rb = bb + T_BH + (uint32_t)((wn * 32 + p * 16) * PITCHB) + b_off + kb;
                uint32_t r[4];
                LDSM4(r, rb);
                Bh[2*p][0] = r[0]; Bh[2*p][1] = r[1];
                Bh[2*p+1][0] = r[2]; Bh[2*p+1][1] = r[3];
                LDSM4(r, rb + (T_BL - T_BH));
                Bl[2*p][0] = r[0]; Bl[2*p][1] = r[1];
                Bl[2*p+1][0] = r[2]; Bl[2*p+1][1] = r[3];
            }
#pragma unroll
            for (int mi = 0; mi < 4; mi++)
#pragma unroll
                for (int ni = 0; ni < 4; ni++) {
                    MMA16816(acc[mi][ni], Ah[mi], Bh[ni][0], Bh[ni][1]);
                    MMA16816(acc[mi][ni], Ah[mi], Bl[ni][0], Bl[ni][1]);
                    MMA16816(acc[mi][ni], Al[mi], Bh[ni][0], Bh[ni][1]);
                }
        }
        __syncthreads();
        if (c + 2 < NC) fill(c + 2, bb);
        CP_COMMIT();   // always commit (possibly empty) to keep group counting
    }
    epi(acc);
}

// -------------------- convert kernels ---------------------------------------
__global__ __launch_bounds__(256)
void cv_split(const float* __restrict__ x, const float* __restrict__ y,
              const float* __restrict__ z)
{
    const int r = blockIdx.x, tid = threadIdx.x;
    if (r < 2048) {
        const int rr = r & 1023;
        const float* s = (r < 1024) ? x : y;
        __nv_bfloat16* H = (r < 1024) ? g_xh : g_yh;
        __nv_bfloat16* L = (r < 1024) ? g_xl : g_yl;
        for (int c = tid; c < KPAD; c += 256) {
            float v = (c < NIN) ? s[(size_t)rr * NIN + c] : (c == NIN ? 1.0f : 0.0f);
            __nv_bfloat16 h = __float2bfloat16(v);
            H[(size_t)rr * KPAD + c] = h;
            L[(size_t)rr * KPAD + c] = __float2bfloat16(v - __bfloat162float(h));
        }
    } else {
        const int rr = r - 2048;
        for (int c = tid; c < NIN; c += 256) {
            float v = z[(size_t)rr * NIN + c];
            __nv_bfloat16 h = __float2bfloat16(v);
            g_zh[(size_t)rr * NIN + c] = h;
            g_zl[(size_t)rr * NIN + c] = __float2bfloat16(v - __bfloat162float(h));
        }
    }
}

// W[i][k][j] -> WT[(j*512+k)][i] hi/lo, i in [0,576) (zeros for i>=513).
__global__ __launch_bounds__(256)
void cv_wt(const float* __restrict__ W)
{
    __shared__ float t[32][33];
    const int k = blockIdx.z, i0 = blockIdx.x * 32, j0 = blockIdx.y * 32;
    const int tx = threadIdx.x, ty = threadIdx.y;
#pragma unroll
    for (int r = 0; r < 4; r++) {
        int i = i0 + ty + r * 8, j = j0 + tx;
        t[ty + r * 8][tx] = (i < IDIM && j < IDIM)
            ? W[((size_t)i * 512 + k) * IDIM + j] : 0.0f;
    }
    __syncthreads();
#pragma unroll
    for (int r = 0; r < 4; r++) {
        int j = j0 + ty + r * 8, i = i0 + tx;
        if (j < IDIM) {
            float v = t[tx][ty + r * 8];
            __nv_bfloat16 h = __float2bfloat16(v);
            size_t o = ((size_t)j * 512 + k) * KPAD + i;
            g_Wh[o] = h;
            g_Wl[o] = __float2bfloat16(v - __bfloat162float(h));
        }
    }
}

// -------------------- GEMM kernels -------------------------------------------
__global__ __launch_bounds__(256) void gemm1()
{
    const int tid = threadIdx.x;
    const int lane = tid & 31, wid = tid >> 5;
    const int wm = wid & 1, wn = wid >> 1;
    const int m0 = blockIdx.x * 128;
    const size_t n0 = (size_t)blockIdx.y * 128;

    auto fill = [&](int ch, uint32_t bb) {
        const int k0 = ch * 32;
#pragma unroll
        for (int v = 0; v < 2; v++) {
            int idx = tid + 256 * v, row = idx >> 2, seg = idx & 3;
            uint32_t d = bb + (uint32_t)(row * PITCHB + seg * 16);
            size_t ak = (size_t)(m0 + row) * KPAD + k0 + seg * 8;
            size_t bk = (n0 + row) * KPAD + k0 + seg * 8;
            CPA16(d,        g_xh + ak);
            CPA16(d + T_AL, g_xl + ak);
            CPA16(d + T_BH, g_Wh + bk);
            CPA16(d + T_BL, g_Wl + bk);
        }
    };
    auto epi = [&](float (&acc)[4][4][4]) {
        const int gid = lane >> 2;
        const size_t coln = n0 + wn * 32 + (lane & 3) * 2;
#pragma unroll
        for (int mi = 0; mi < 4; mi++)
#pragma unroll
            for (int half = 0; half < 2; half++) {
                size_t rb = (size_t)(m0 + wm * 64 + mi * 16 + gid + half * 8) * NWL + coln;
#pragma unroll
                for (int ni = 0; ni < 4; ni++) {
                    uint32_t hw, lw;
                    hl_pack(acc[mi][ni][half * 2], acc[mi][ni][half * 2 + 1], hw, lw);
                    *reinterpret_cast<uint32_t*>(g_Xh + rb + ni * 8) = hw;
                    *reinterpret_cast<uint32_t*>(g_Xl + rb + ni * 8) = lw;
                }
            }
    };
    mm_body<18>(fill, epi);
}

__global__ __launch_bounds__(256) void gemm2()
{
    const int tid = threadIdx.x;
    const int lane = tid & 31, wid = tid >> 5;
    const int wm = wid & 1, wn = wid >> 1;
    const int n0 = blockIdx.x * 128;          // j-tile
    const int bx = blockIdx.y, b = bx >> 7;

    auto fill = [&](int ch, uint32_t bb) {
        const int k0 = ch * 32;
#pragma unroll
        for (int v = 0; v < 2; v++) {
            int idx = tid + 256 * v, row = idx >> 2, seg = idx & 3;
            uint32_t d = bb + (uint32_t)(row * PITCHB + seg * 16);
            size_t ak = (size_t)(b * 128 + row) * NIN + k0 + seg * 8;
            int j = n0 + row;
            int jc = (j < IDIM) ? j : 512;
            size_t bk = (size_t)bx * NWL + (size_t)jc * 512 + k0 + seg * 8;
            CPA16(d,        g_zh + ak);
            CPA16(d + T_AL, g_zl + ak);
            CPA16(d + T_BH, g_Xh + bk);
            CPA16(d + T_BL, g_Xl + bk);
        }
    };
    auto epi = [&](float (&acc)[4][4][4]) {
        const int gid = lane >> 2;
#pragma unroll
        for (int mi = 0; mi < 4; mi++)
#pragma unroll
            for (int half = 0; half < 2; half++) {
                int zz = wm * 64 + mi * 16 + gid + half * 8;
                size_t rb = ((size_t)bx * 128 + zz) * TP;
#pragma unroll
                for (int ni = 0; ni < 4; ni++) {
                    int j = n0 + wn * 32 + ni * 8 + (lane & 3) * 2;
                    if (j <= 512) {
                        float v0 = acc[mi][ni][half * 2];
                        float v1 = (j + 1 <= 512) ? acc[mi][ni][half * 2 + 1] : 0.0f;
                        uint32_t hw, lw;
                        hl_pack(v0, v1, hw, lw);   // j==512 -> col513 stays 0
                        *reinterpret_cast<uint32_t*>(g_Th + rb + j) = hw;
                        *reinterpret_cast<uint32_t*>(g_Tl + rb + j) = lw;
                    }
                }
            }
    };
    mm_body<16>(fill, epi);
}

__global__ __launch_bounds__(256) void gemm3(float* __restrict__ out)
{
    const int tid = threadIdx.x;
    const int lane = tid & 31, wid = tid >> 5;
    const int wm = wid & 1, wn = wid >> 1;
    const int bx = blockIdx.x, b = bx >> 7, xx = bx & 127;

    auto fill = [&](int ch, uint32_t bb) {
        const int k0 = ch * 32;
#pragma unroll
        for (int v = 0; v < 2; v++) {
            int idx = tid + 256 * v, row = idx >> 2, seg = idx & 3;
            uint32_t d = bb + (uint32_t)(row * PITCHB + seg * 16);
            size_t ak = ((size_t)bx * 128 + row) * TP + k0 + seg * 8;
            size_t bk = (size_t)(b * 128 + row) * KPAD + k0 + seg * 8;
            CPA16(d,        g_Th + ak);
            CPA16(d + T_AL, g_Tl + ak);
            CPA16(d + T_BH, g_yh + bk);
            CPA16(d + T_BL, g_yl + bk);
        }
    };
    auto epi = [&](float (&acc)[4][4][4]) {
        const int gid = lane >> 2;
#pragma unroll
        for (int mi = 0; mi < 4; mi++)
#pragma unroll
            for (int half = 0; half < 2; half++) {
                int zz = wm * 64 + mi * 16 + gid + half * 8;
                float* o = out + ((size_t)(b * 128 + zz) * 128 + xx) * 128
                               + wn * 32 + (lane & 3) * 2;
#pragma unroll
                for (int ni = 0; ni < 4; ni++) {
                    float2 v = make_float2(acc[mi][ni][half * 2],
                                           acc[mi][ni][half * 2 + 1]);
                    *reinterpret_cast<float2*>(o + ni * 8) = v;
                }
            }
    };
    mm_body<18>(fill, epi);
}

// ----------------------------------------------------------------------------
extern "C" void kernel_launch(void* const* d_in, const int* in_sizes, int n_in,
                              void* d_out, int out_size)
{
    const float* x = (const float*)d_in[0];
    const float* y = (const float*)d_in[1];
    const float* z = (const float*)d_in[2];
    const float* w = (const float*)d_in[3];
    float* out = (float*)d_out;

    cudaFuncSetAttribute(gemm1, cudaFuncAttributeMaxDynamicSharedMemorySize, SMEMB);
    cudaFuncSetAttribute(gemm2, cudaFuncAttributeMaxDynamicSharedMemorySize, SMEMB);
    cudaFuncSetAttribute(gemm3, cudaFuncAttributeMaxDynamicSharedMemorySize, SMEMB);

    cv_split<<<3072, 256>>>(x, y, z);
    cv_wt<<<dim3(18, 17, 512), dim3(32, 8)>>>(w);
    gemm1<<<dim3(8, 2052), 256, SMEMB>>>();
    gemm2<<<dim3(5, 1024), 256, SMEMB>>>();
    gemm3<<<1024, 256, SMEMB>>>(out);
}